// round 15
// baseline (speedup 1.0000x reference)
#include <cuda_runtime.h>
#include <cuda_fp16.h>
#include <cuda_bf16.h>
#include <stdint.h>

#define N_NODES 100000
#define N_EDGES 3200000
#define F_IN 256
#define HID 64
#define N_CLS 16
#define LOG2E 1.4426950408889634f
#define LB_MASK ((1 << 28) - 1)

// ---------------- scratch (static device globals; no allocation) -------------
__device__ float  g_h1f[N_NODES * HID];     // fp32 projected feats (gemm1 out)
__device__ __half2 g_h1h[N_NODES * HID / 2];// fp16 alpha-folded feats, [n][32] half2
__device__ __half g_h2h[N_NODES * N_CLS];   // fp16 layer2 feats (rsum2 folded)
__device__ float  g_rsum2[N_NODES * N_CLS];
__device__ float  g_cp1[HID], g_cm1[HID], g_cp2[N_CLS], g_cm2[N_CLS]; // pre-scaled by log2(e)
__device__ int    g_cnt[2 * N_NODES];       // counts
__device__ int    g_off[2 * (N_NODES + 1)]; // [0..N] src offsets, [N+1..2N+1] dst offsets
__device__ int    g_cur[2 * N_NODES];
__device__ int    g_scanst[1 + 256];        // [0]=ticket, [1+b]=packed lookback word
__device__ float  g_srcw[N_EDGES];          // w values in src-CSR order
__device__ float2 g_dstp[N_EDGES];          // (w, as_float(src)) in dst-CSR order

// host-side stream/event resources, created at static-init (no device alloc)
struct HxStreams {
    cudaStream_t s2;
    cudaEvent_t ev0, evB;
    HxStreams() {
        cudaStreamCreateWithFlags(&s2, cudaStreamNonBlocking);
        cudaEventCreateWithFlags(&ev0, cudaEventDisableTiming);
        cudaEventCreateWithFlags(&evB, cudaEventDisableTiming);
    }
};
static HxStreams g_hx;

__device__ __forceinline__ float fex2(float x) {
    float y;
    asm("ex2.approx.ftz.f32 %0, %1;" : "=f"(y) : "f"(x));
    return y;
}
__device__ __forceinline__ float flg2(float x) {
    float y;
    asm("lg2.approx.ftz.f32 %0, %1;" : "=f"(y) : "f"(x));
    return y;
}
// dual fp16 exp2 in ONE MUFU op — scalar register in/out, no addressable temps
__device__ __forceinline__ __half2 hx_ex2_h2(__half2 v) {
    unsigned u = reinterpret_cast<unsigned&>(v);
    asm("ex2.approx.f16x2 %0, %0;" : "+r"(u));
    return reinterpret_cast<__half2&>(u);
}
// packed f32x2 fma (FFMA2) — only reachable via PTX
__device__ __forceinline__ void ffma2(unsigned long long& acc, unsigned long long a, unsigned long long b) {
    asm("fma.rn.f32x2 %0, %1, %2, %0;" : "+l"(acc) : "l"(a), "l"(b));
}
__device__ __forceinline__ unsigned long long pack2(float v) {
    unsigned long long r;
    asm("mov.b64 %0, {%1, %1};" : "=l"(r) : "f"(v));
    return r;
}
__device__ __forceinline__ float2 unpack2(unsigned long long v) {
    float lo, hi;
    asm("mov.b64 {%0, %1}, %2;" : "=f"(lo), "=f"(hi) : "l"(v));
    return make_float2(lo, hi);
}

// ------- prep_zero: blocks 0..195 zero cnt; block 196 zeros scanst + coefs ----
__global__ void prep_zero_kernel(const float* __restrict__ m1w0, const float* __restrict__ m1w1,
                                 const float* __restrict__ m2w0, const float* __restrict__ m2w1) {
    if (blockIdx.x < 196) {
        int i = blockIdx.x * 1024 + threadIdx.x;
        if (i < 2 * N_NODES) g_cnt[i] = 0;
        return;
    }
    int t = threadIdx.x;
    if (t < 1 + 256) g_scanst[t] = 0;
    if (t >= 512) {             // coef work on a separate warp-group
        int c = t - 512;
        if (c < HID) {
            float sp = 0.f, sm = 0.f;
            for (int k = 0; k < HID; k++) {
                float w0 = m1w0[k];
                float ap = (w0 >= 0.f) ? w0 : 0.2f * w0;
                float am = (w0 >= 0.f) ? 0.2f * w0 : w0;
                float w1 = m1w1[c * HID + k];
                sp = fmaf(w1, ap, sp);
                sm = fmaf(w1, am, sm);
            }
            g_cp1[c] = sp * LOG2E; g_cm1[c] = sm * LOG2E;
        } else if (c < HID + N_CLS) {
            int cc = c - HID;
            float sp = 0.f, sm = 0.f;
            for (int k = 0; k < HID; k++) {
                float w0 = m2w0[k];
                float ap = (w0 >= 0.f) ? w0 : 0.2f * w0;
                float am = (w0 >= 0.f) ? 0.2f * w0 : w0;
                float w2 = m2w1[cc * HID + k];
                sp = fmaf(w2, ap, sp);
                sm = fmaf(w2, am, sm);
            }
            g_cp2[cc] = sp * LOG2E; g_cm2[cc] = sm * LOG2E;
        }
    }
}

// ---------------- CSR build ---------------------------------------------------
__global__ void hist_kernel(const int* __restrict__ ei) {
    int b = (blockIdx.x * blockDim.x + threadIdx.x) * 4;
    if (b >= N_EDGES) return;
    int4 s = *(const int4*)&ei[b];
    atomicAdd(&g_cnt[s.x], 1);
    atomicAdd(&g_cnt[s.y], 1);
    atomicAdd(&g_cnt[s.z], 1);
    atomicAdd(&g_cnt[s.w], 1);
    int4 d = *(const int4*)&ei[N_EDGES + b];
    atomicAdd(&g_cnt[N_NODES + d.x], 1);
    atomicAdd(&g_cnt[N_NODES + d.y], 1);
    atomicAdd(&g_cnt[N_NODES + d.z], 1);
    atomicAdd(&g_cnt[N_NODES + d.w], 1);
}

// single-pass decoupled-lookback exclusive scan over g_cnt[0..2N)
__global__ void scan_lb_kernel() {
    __shared__ int sbid, s_prev;
    __shared__ int wsum[32];
    if (threadIdx.x == 0) sbid = atomicAdd(&g_scanst[0], 1);
    __syncthreads();
    int bid = sbid;
    int i = bid * 1024 + threadIdx.x;
    int lane = threadIdx.x & 31, wid = threadIdx.x >> 5;
    int v = (i < 2 * N_NODES) ? g_cnt[i] : 0;
    int incl = v;
#pragma unroll
    for (int d = 1; d < 32; d <<= 1) {
        int t = __shfl_up_sync(0xffffffffu, incl, d);
        if (lane >= d) incl += t;
    }
    if (lane == 31) wsum[wid] = incl;
    __syncthreads();
    if (wid == 0) {
        int s = wsum[lane];
        int si = s;
#pragma unroll
        for (int d = 1; d < 32; d <<= 1) {
            int t = __shfl_up_sync(0xffffffffu, si, d);
            if (lane >= d) si += t;
        }
        wsum[lane] = si - s;
    }
    __syncthreads();
    int excl = incl - v + wsum[wid];
    int* lb = &g_scanst[1];
    if (threadIdx.x == 1023) {
        int tot = excl + v;
        if (bid == 0) {
            atomicExch(&lb[0], (2 << 28) | tot);
            s_prev = 0;
        } else {
            atomicExch(&lb[bid], (1 << 28) | tot);
            int prev = 0;
            int j = bid - 1;
            while (true) {
                int w;
                do { w = atomicAdd(&lb[j], 0); } while (w == 0);
                prev += (w & LB_MASK);
                if ((w >> 28) == 2) break;
                j--;
            }
            atomicExch(&lb[bid], (2 << 28) | (prev + tot));
            s_prev = prev;
        }
    }
    __syncthreads();
    int pref = excl + s_prev;
    if (i < 2 * N_NODES) {
        if (i < N_NODES) {
            g_off[i] = pref;
            g_cur[i] = pref;
        } else {
            int d = i - N_NODES;
            g_off[N_NODES + 1 + d] = pref - N_EDGES;
            g_cur[i] = pref - N_EDGES;
        }
    }
    if (i == 0) {
        g_off[N_NODES] = N_EDGES;
        g_off[2 * N_NODES + 1] = N_EDGES;
    }
}

__global__ void scatter_kernel(const int* __restrict__ ei, const float* __restrict__ wmul) {
    int b = (blockIdx.x * blockDim.x + threadIdx.x) * 4;
    if (b >= N_EDGES) return;
    int4 s4 = *(const int4*)&ei[b];
    int4 d4 = *(const int4*)&ei[N_EDGES + b];
    float4 w4 = *(const float4*)&wmul[b];
    int p;
    p = atomicAdd(&g_cur[s4.x], 1); g_srcw[p] = w4.x;
    p = atomicAdd(&g_cur[s4.y], 1); g_srcw[p] = w4.y;
    p = atomicAdd(&g_cur[s4.z], 1); g_srcw[p] = w4.z;
    p = atomicAdd(&g_cur[s4.w], 1); g_srcw[p] = w4.w;
    p = atomicAdd(&g_cur[N_NODES + d4.x], 1); g_dstp[p] = make_float2(w4.x, __int_as_float(s4.x));
    p = atomicAdd(&g_cur[N_NODES + d4.y], 1); g_dstp[p] = make_float2(w4.y, __int_as_float(s4.y));
    p = atomicAdd(&g_cur[N_NODES + d4.z], 1); g_dstp[p] = make_float2(w4.z, __int_as_float(s4.z));
    p = atomicAdd(&g_cur[N_NODES + d4.w], 1); g_dstp[p] = make_float2(w4.w, __int_as_float(s4.w));
}

// ---- GEMM1: h1f = x @ lin1_w^T + b; weight transposed in-kernel via smem -----
#define G1_BN 128
#define G1_BK 32
__global__ void gemm1_kernel(const float* __restrict__ x, const float* __restrict__ lin1_w,
                             const float* __restrict__ b1) {
    __shared__ __align__(16) float xs[G1_BN][33];
    __shared__ __align__(16) float ws[G1_BK][HID + 4];  // 68-float rows: 16B-aligned, 4-way-conflict stores
    int tid = threadIdx.x;         // 256
    int nb = blockIdx.x * G1_BN;
    int jg = tid & 7;
    int ng = tid >> 3;
    unsigned long long acc2[4][4];
#pragma unroll
    for (int i = 0; i < 4; i++)
#pragma unroll
        for (int p = 0; p < 4; p++) acc2[i][p] = 0ull;

    for (int k0 = 0; k0 < F_IN; k0 += G1_BK) {
        for (int i = tid; i < G1_BN * G1_BK; i += 256) {
            int n = i >> 5, kk = i & 31;
            int gn = nb + n;
            xs[n][kk] = (gn < N_NODES) ? x[gn * F_IN + k0 + kk] : 0.f;
        }
        // transpose-load lin1_w tile: coalesced read of rows j, cols k0+col
        for (int i = tid; i < HID * G1_BK; i += 256) {
            int j = i >> 5, col = i & 31;
            ws[col][j] = lin1_w[j * F_IN + k0 + col];
        }
        __syncthreads();
#pragma unroll
        for (int kk = 0; kk < G1_BK; kk++) {
            ulonglong2 wa = *(const ulonglong2*)&ws[kk][jg * 8];
            ulonglong2 wb = *(const ulonglong2*)&ws[kk][jg * 8 + 4];
#pragma unroll
            for (int i = 0; i < 4; i++) {
                unsigned long long xx = pack2(xs[ng * 4 + i][kk]);
                ffma2(acc2[i][0], xx, wa.x);
                ffma2(acc2[i][1], xx, wa.y);
                ffma2(acc2[i][2], xx, wb.x);
                ffma2(acc2[i][3], xx, wb.y);
            }
        }
        __syncthreads();
    }
    float bj[8];
#pragma unroll
    for (int r = 0; r < 8; r++) bj[r] = b1[jg * 8 + r];
#pragma unroll
    for (int i = 0; i < 4; i++) {
        int gn = nb + ng * 4 + i;
        if (gn < N_NODES) {
            float2 p0 = unpack2(acc2[i][0]);
            float2 p1 = unpack2(acc2[i][1]);
            float2 p2 = unpack2(acc2[i][2]);
            float2 p3 = unpack2(acc2[i][3]);
            float4 v0 = make_float4(p0.x + bj[0], p0.y + bj[1], p1.x + bj[2], p1.y + bj[3]);
            float4 v1 = make_float4(p2.x + bj[4], p2.y + bj[5], p3.x + bj[6], p3.y + bj[7]);
            *(float4*)&g_h1f[gn * HID + jg * 8]     = v0;
            *(float4*)&g_h1f[gn * HID + jg * 8 + 4] = v1;
        }
    }
}

// ---------- merged pass1: rsum over src segments; emit fp16 h1 ----------------
// f16x2 ex2: one MUFU per feature pair; wp/wm split instead of setp+sel
__global__ void pass1_kernel() {
    int warp = (blockIdx.x * blockDim.x + threadIdx.x) >> 5;
    int lane = threadIdx.x & 31;
    if (warp >= N_NODES) return;
    int j0 = 2 * lane, j1 = 2 * lane + 1;
    float cpa = g_cp1[j0], cma = g_cm1[j0];
    float cpb = g_cp1[j1], cmb = g_cm1[j1];
    const __half2 hcl = __floats2half2_rn(14.f, 14.f);
    int beg = g_off[warp], end = g_off[warp + 1];
    float a0 = 0.f, a1 = 0.f;
#pragma unroll 4
    for (int i = beg; i < end; i++) {
        float w = __ldg(&g_srcw[i]);
        float wp = fmaxf(w, 0.f), wm = fminf(w, 0.f);
        float m0 = fmaf(wp, cpa, wm * cma);
        float m1 = fmaf(wp, cpb, wm * cmb);
        __half2 e = hx_ex2_h2(__hmin2(__floats2half2_rn(m0, m1), hcl));
        float2 ef = __half22float2(e);
        a0 += ef.x;
        a1 += ef.y;
    }
    // layer-2 sums: 8 class-pairs x 4 edge-subs
    int cc = lane & 7, sub = lane >> 3;
    float cpc0 = g_cp2[2 * cc],     cmc0 = g_cm2[2 * cc];
    float cpc1 = g_cp2[2 * cc + 1], cmc1 = g_cm2[2 * cc + 1];
    float a2x = 0.f, a2y = 0.f;
#pragma unroll 2
    for (int i = beg + sub; i < end; i += 4) {
        float w = __ldg(&g_srcw[i]);
        float wp = fmaxf(w, 0.f), wm = fminf(w, 0.f);
        float m0 = fmaf(wp, cpc0, wm * cmc0);
        float m1 = fmaf(wp, cpc1, wm * cmc1);
        __half2 e = hx_ex2_h2(__hmin2(__floats2half2_rn(m0, m1), hcl));
        float2 ef = __half22float2(e);
        a2x += ef.x;
        a2y += ef.y;
    }
    a2x += __shfl_xor_sync(0xffffffffu, a2x, 8);
    a2x += __shfl_xor_sync(0xffffffffu, a2x, 16);
    a2y += __shfl_xor_sync(0xffffffffu, a2y, 8);
    a2y += __shfl_xor_sync(0xffffffffu, a2y, 16);
    float r0 = 1.f / (a0 + 1e-16f);
    float r1 = 1.f / (a1 + 1e-16f);
    float2 hf = *(const float2*)&g_h1f[warp * HID + j0];
    g_h1h[warp * 32 + lane] = __floats2half2_rn(hf.x * r0, hf.y * r1);
    if (lane < 8)
        *(float2*)&g_rsum2[warp * N_CLS + 2 * cc] =
            make_float2(1.f / (a2x + 1e-16f), 1.f / (a2y + 1e-16f));
}

// ---------- layer1 pass2 over dst (fp16 gather) + fused elu + GEMM2 -----------
// alpha folded into h1h: fp16 product |e*(h*r)| <= |h| so no overflow
__global__ void pass2_l1_kernel(const float* __restrict__ lin2_w, const float* __restrict__ lin2_b) {
    __shared__ float ws[HID][N_CLS + 1];
    __shared__ float bs[N_CLS];
    __shared__ float sagg[8][HID + 1];
    int tid = threadIdx.x;
    int wid = tid >> 5;
    int lane = tid & 31;
    int warp = blockIdx.x * 8 + wid;
    for (int i = tid; i < N_CLS * HID; i += 256) {
        int c = i >> 6, k = i & 63;
        ws[k][c] = lin2_w[i];
    }
    if (tid < N_CLS) bs[tid] = lin2_b[tid];

    int j0 = 2 * lane, j1 = 2 * lane + 1;
    float cpa = g_cp1[j0], cma = g_cm1[j0];
    float cpb = g_cp1[j1], cmb = g_cm1[j1];
    const __half2 hcl = __floats2half2_rn(14.f, 14.f);
    const int* doff = g_off + (N_NODES + 1);
    int beg = doff[warp], end = doff[warp + 1];
    float a0 = 0.f, a1 = 0.f;
#pragma unroll 4
    for (int i = beg; i < end; i++) {
        float2 p = __ldg(&g_dstp[i]);
        float w = p.x;
        int s = __float_as_int(p.y);
        float wp = fmaxf(w, 0.f), wm = fminf(w, 0.f);
        float m0 = fmaf(wp, cpa, wm * cma);
        float m1 = fmaf(wp, cpb, wm * cmb);
        __half2 e = hx_ex2_h2(__hmin2(__floats2half2_rn(m0, m1), hcl));
        __half2 prod = __hmul2(e, g_h1h[s * 32 + lane]);
        float2 pf = __half22float2(prod);
        a0 += pf.x;
        a1 += pf.y;
    }
    sagg[wid][j0] = (a0 > 0.f) ? a0 : (fex2(a0 * LOG2E) - 1.f);
    sagg[wid][j1] = (a1 > 0.f) ? a1 : (fex2(a1 * LOG2E) - 1.f);
    __syncthreads();
    if (tid < 128) {
        int n = tid >> 4, c = tid & 15;
        int node = blockIdx.x * 8 + n;
        float acc = bs[c];
#pragma unroll
        for (int k = 0; k < HID; k++) acc = fmaf(sagg[n][k], ws[k][c], acc);
        g_h2h[node * N_CLS + c] = __float2half(acc * g_rsum2[node * N_CLS + c]);
    }
}

// ---------- layer2 pass2 over dst + fused log_softmax -> out (fp32 exp) -------
__global__ void pass2_l2_kernel(float* __restrict__ out) {
    int warp = (blockIdx.x * blockDim.x + threadIdx.x) >> 5;
    int lane = threadIdx.x & 31;
    if (warp >= N_NODES) return;
    int j = lane & 15, sub = lane >> 4;
    float cp = g_cp2[j], cm = g_cm2[j];
    const int* doff = g_off + (N_NODES + 1);
    int beg = doff[warp], end = doff[warp + 1];
    float a = 0.f;
#pragma unroll 2
    for (int i = beg + sub; i < end; i += 2) {
        float2 p = __ldg(&g_dstp[i]);
        float w = p.x;
        int s = __float_as_int(p.y);
        float c = (w >= 0.f) ? cp : cm;
        a = fmaf(fex2(w * c), __half2float(g_h2h[s * N_CLS + j]), a);
    }
    a += __shfl_xor_sync(0xffffffffu, a, 16);
    float m = a;
#pragma unroll
    for (int k = 8; k >= 1; k >>= 1) m = fmaxf(m, __shfl_xor_sync(0xffffffffu, m, k));
    float ex = fex2((a - m) * LOG2E);
    float ssum = ex;
#pragma unroll
    for (int k = 8; k >= 1; k >>= 1) ssum += __shfl_xor_sync(0xffffffffu, ssum, k);
    float res = a - m - flg2(ssum) * 0.69314718055994531f;
    if (lane < 16) out[warp * N_CLS + lane] = res;
}

// ---------------- launch ------------------------------------------------------
extern "C" void kernel_launch(void* const* d_in, const int* in_sizes, int n_in,
                              void* d_out, int out_size) {
    const float* x      = (const float*)d_in[0];
    const int*   ei     = (const int*)  d_in[1];
    const float* wmul   = (const float*)d_in[2];
    const float* lin1_w = (const float*)d_in[3];
    const float* lin1_b = (const float*)d_in[4];
    const float* m1w0   = (const float*)d_in[5];
    const float* m1w1   = (const float*)d_in[6];
    // d_in[7] = mlp1_b1 (cancels in softmax)
    const float* lin2_w = (const float*)d_in[8];
    const float* lin2_b = (const float*)d_in[9];
    const float* m2w0   = (const float*)d_in[10];
    const float* m2w1   = (const float*)d_in[11];
    // d_in[12] = mlp2_b1 (cancels in softmax)
    float* out = (float*)d_out;

    (void)in_sizes; (void)n_in; (void)out_size;

    const int nblk_scan = (2 * N_NODES + 1023) / 1024;  // 196

    // fork: CSR build (+zero+coefs) on side stream, gemm1 immediately on main
    cudaEventRecord(g_hx.ev0, 0);
    cudaStreamWaitEvent(g_hx.s2, g_hx.ev0, 0);

    prep_zero_kernel<<<197, 1024, 0, g_hx.s2>>>(m1w0, m1w1, m2w0, m2w1);
    hist_kernel<<<(N_EDGES / 4 + 255) / 256, 256, 0, g_hx.s2>>>(ei);
    scan_lb_kernel<<<nblk_scan, 1024, 0, g_hx.s2>>>();
    scatter_kernel<<<(N_EDGES / 4 + 255) / 256, 256, 0, g_hx.s2>>>(ei, wmul);
    cudaEventRecord(g_hx.evB, g_hx.s2);

    gemm1_kernel<<<(N_NODES + G1_BN - 1) / G1_BN, 256>>>(x, lin1_w, lin1_b);

    // join
    cudaStreamWaitEvent(0, g_hx.evB, 0);

    pass1_kernel<<<(N_NODES * 32 + 255) / 256, 256>>>();
    pass2_l1_kernel<<<(N_NODES * 32 + 255) / 256, 256>>>(lin2_w, lin2_b);
    pass2_l2_kernel<<<(N_NODES * 32 + 255) / 256, 256>>>(out);
}

// round 16
// speedup vs baseline: 1.0486x; 1.0486x over previous
#include <cuda_runtime.h>
#include <cuda_fp16.h>
#include <cuda_bf16.h>
#include <stdint.h>

#define N_NODES 100000
#define N_EDGES 3200000
#define F_IN 256
#define HID 64
#define N_CLS 16
#define LOG2E 1.4426950408889634f
#define LB_MASK ((1 << 28) - 1)

// ---------------- scratch (static device globals; no allocation) -------------
__device__ float  g_h1f[N_NODES * HID];     // fp32 projected feats (gemm1 out)
__device__ __half2 g_h1h[N_NODES * HID / 2];// fp16 alpha-folded feats, [n][32] half2
__device__ __half g_h2h[N_NODES * N_CLS];   // fp16 layer2 feats (rsum2 folded)
__device__ float  g_rsum2[N_NODES * N_CLS];
__device__ float  g_cp1[HID], g_cm1[HID], g_cp2[N_CLS], g_cm2[N_CLS]; // pre-scaled by log2(e)
__device__ int    g_cnt[2 * N_NODES];       // counts
__device__ int    g_off[2 * (N_NODES + 1)]; // [0..N] src offsets, [N+1..2N+1] dst offsets
__device__ int    g_cur[2 * N_NODES];
__device__ int    g_scanst[1 + 256];        // [0]=ticket, [1+b]=packed lookback word
__device__ float  g_srcw[N_EDGES];          // w values in src-CSR order
__device__ float2 g_dstp[N_EDGES];          // (w, as_float(src)) in dst-CSR order

// host-side stream/event resources, created at static-init (no device alloc)
struct HxStreams {
    cudaStream_t s2;
    cudaEvent_t ev0, evB, evC;
    HxStreams() {
        cudaStreamCreateWithFlags(&s2, cudaStreamNonBlocking);
        cudaEventCreateWithFlags(&ev0, cudaEventDisableTiming);
        cudaEventCreateWithFlags(&evB, cudaEventDisableTiming);
        cudaEventCreateWithFlags(&evC, cudaEventDisableTiming);
    }
};
static HxStreams g_hx;

__device__ __forceinline__ float fex2(float x) {
    float y;
    asm("ex2.approx.ftz.f32 %0, %1;" : "=f"(y) : "f"(x));
    return y;
}
__device__ __forceinline__ float flg2(float x) {
    float y;
    asm("lg2.approx.ftz.f32 %0, %1;" : "=f"(y) : "f"(x));
    return y;
}
// packed f32x2 fma (FFMA2) — only reachable via PTX
__device__ __forceinline__ void ffma2(unsigned long long& acc, unsigned long long a, unsigned long long b) {
    asm("fma.rn.f32x2 %0, %1, %2, %0;" : "+l"(acc) : "l"(a), "l"(b));
}
__device__ __forceinline__ unsigned long long pack2(float v) {
    unsigned long long r;
    asm("mov.b64 %0, {%1, %1};" : "=l"(r) : "f"(v));
    return r;
}
__device__ __forceinline__ float2 unpack2(unsigned long long v) {
    float lo, hi;
    asm("mov.b64 {%0, %1}, %2;" : "=f"(lo), "=f"(hi) : "l"(v));
    return make_float2(lo, hi);
}

// ------- prep_zero: blocks 0..195 zero cnt; block 196 zeros scanst + coefs ----
__global__ void prep_zero_kernel(const float* __restrict__ m1w0, const float* __restrict__ m1w1,
                                 const float* __restrict__ m2w0, const float* __restrict__ m2w1) {
    if (blockIdx.x < 196) {
        int i = blockIdx.x * 1024 + threadIdx.x;
        if (i < 2 * N_NODES) g_cnt[i] = 0;
        return;
    }
    int t = threadIdx.x;
    if (t < 1 + 256) g_scanst[t] = 0;
    if (t >= 512) {             // coef work on a separate warp-group
        int c = t - 512;
        if (c < HID) {
            float sp = 0.f, sm = 0.f;
            for (int k = 0; k < HID; k++) {
                float w0 = m1w0[k];
                float ap = (w0 >= 0.f) ? w0 : 0.2f * w0;
                float am = (w0 >= 0.f) ? 0.2f * w0 : w0;
                float w1 = m1w1[c * HID + k];
                sp = fmaf(w1, ap, sp);
                sm = fmaf(w1, am, sm);
            }
            g_cp1[c] = sp * LOG2E; g_cm1[c] = sm * LOG2E;
        } else if (c < HID + N_CLS) {
            int cc = c - HID;
            float sp = 0.f, sm = 0.f;
            for (int k = 0; k < HID; k++) {
                float w0 = m2w0[k];
                float ap = (w0 >= 0.f) ? w0 : 0.2f * w0;
                float am = (w0 >= 0.f) ? 0.2f * w0 : w0;
                float w2 = m2w1[cc * HID + k];
                sp = fmaf(w2, ap, sp);
                sm = fmaf(w2, am, sm);
            }
            g_cp2[cc] = sp * LOG2E; g_cm2[cc] = sm * LOG2E;
        }
    }
}

// ---------------- CSR build ---------------------------------------------------
__global__ void hist_kernel(const int* __restrict__ ei) {
    int b = (blockIdx.x * blockDim.x + threadIdx.x) * 4;
    if (b >= N_EDGES) return;
    int4 s = *(const int4*)&ei[b];
    atomicAdd(&g_cnt[s.x], 1);
    atomicAdd(&g_cnt[s.y], 1);
    atomicAdd(&g_cnt[s.z], 1);
    atomicAdd(&g_cnt[s.w], 1);
    int4 d = *(const int4*)&ei[N_EDGES + b];
    atomicAdd(&g_cnt[N_NODES + d.x], 1);
    atomicAdd(&g_cnt[N_NODES + d.y], 1);
    atomicAdd(&g_cnt[N_NODES + d.z], 1);
    atomicAdd(&g_cnt[N_NODES + d.w], 1);
}

// single-pass decoupled-lookback exclusive scan over g_cnt[0..2N)
__global__ void scan_lb_kernel() {
    __shared__ int sbid, s_prev;
    __shared__ int wsum[32];
    if (threadIdx.x == 0) sbid = atomicAdd(&g_scanst[0], 1);
    __syncthreads();
    int bid = sbid;
    int i = bid * 1024 + threadIdx.x;
    int lane = threadIdx.x & 31, wid = threadIdx.x >> 5;
    int v = (i < 2 * N_NODES) ? g_cnt[i] : 0;
    int incl = v;
#pragma unroll
    for (int d = 1; d < 32; d <<= 1) {
        int t = __shfl_up_sync(0xffffffffu, incl, d);
        if (lane >= d) incl += t;
    }
    if (lane == 31) wsum[wid] = incl;
    __syncthreads();
    if (wid == 0) {
        int s = wsum[lane];
        int si = s;
#pragma unroll
        for (int d = 1; d < 32; d <<= 1) {
            int t = __shfl_up_sync(0xffffffffu, si, d);
            if (lane >= d) si += t;
        }
        wsum[lane] = si - s;
    }
    __syncthreads();
    int excl = incl - v + wsum[wid];
    int* lb = &g_scanst[1];
    if (threadIdx.x == 1023) {
        int tot = excl + v;
        if (bid == 0) {
            atomicExch(&lb[0], (2 << 28) | tot);
            s_prev = 0;
        } else {
            atomicExch(&lb[bid], (1 << 28) | tot);
            int prev = 0;
            int j = bid - 1;
            while (true) {
                int w;
                do { w = atomicAdd(&lb[j], 0); } while (w == 0);
                prev += (w & LB_MASK);
                if ((w >> 28) == 2) break;
                j--;
            }
            atomicExch(&lb[bid], (2 << 28) | (prev + tot));
            s_prev = prev;
        }
    }
    __syncthreads();
    int pref = excl + s_prev;
    if (i < 2 * N_NODES) {
        if (i < N_NODES) {
            g_off[i] = pref;
            g_cur[i] = pref;
        } else {
            int d = i - N_NODES;
            g_off[N_NODES + 1 + d] = pref - N_EDGES;
            g_cur[i] = pref - N_EDGES;
        }
    }
    if (i == 0) {
        g_off[N_NODES] = N_EDGES;
        g_off[2 * N_NODES + 1] = N_EDGES;
    }
}

// src-side scatter only: fills g_srcw (pass1's input)
__global__ void scatter_src_kernel(const int* __restrict__ ei, const float* __restrict__ wmul) {
    int b = (blockIdx.x * blockDim.x + threadIdx.x) * 4;
    if (b >= N_EDGES) return;
    int4 s4 = *(const int4*)&ei[b];
    float4 w4 = *(const float4*)&wmul[b];
    int p;
    p = atomicAdd(&g_cur[s4.x], 1); g_srcw[p] = w4.x;
    p = atomicAdd(&g_cur[s4.y], 1); g_srcw[p] = w4.y;
    p = atomicAdd(&g_cur[s4.z], 1); g_srcw[p] = w4.z;
    p = atomicAdd(&g_cur[s4.w], 1); g_srcw[p] = w4.w;
}

// dst-side scatter: fills g_dstp (pass2's input); overlaps with pass1
__global__ void scatter_dst_kernel(const int* __restrict__ ei, const float* __restrict__ wmul) {
    int b = (blockIdx.x * blockDim.x + threadIdx.x) * 4;
    if (b >= N_EDGES) return;
    int4 s4 = *(const int4*)&ei[b];
    int4 d4 = *(const int4*)&ei[N_EDGES + b];
    float4 w4 = *(const float4*)&wmul[b];
    int p;
    p = atomicAdd(&g_cur[N_NODES + d4.x], 1); g_dstp[p] = make_float2(w4.x, __int_as_float(s4.x));
    p = atomicAdd(&g_cur[N_NODES + d4.y], 1); g_dstp[p] = make_float2(w4.y, __int_as_float(s4.y));
    p = atomicAdd(&g_cur[N_NODES + d4.z], 1); g_dstp[p] = make_float2(w4.z, __int_as_float(s4.z));
    p = atomicAdd(&g_cur[N_NODES + d4.w], 1); g_dstp[p] = make_float2(w4.w, __int_as_float(s4.w));
}

// ---- GEMM1: h1f = x @ lin1_w^T + b; weight transposed in-kernel via smem -----
#define G1_BN 128
#define G1_BK 32
__global__ void gemm1_kernel(const float* __restrict__ x, const float* __restrict__ lin1_w,
                             const float* __restrict__ b1) {
    __shared__ __align__(16) float xs[G1_BN][33];
    __shared__ __align__(16) float ws[G1_BK][HID + 4];
    int tid = threadIdx.x;         // 256
    int nb = blockIdx.x * G1_BN;
    int jg = tid & 7;
    int ng = tid >> 3;
    unsigned long long acc2[4][4];
#pragma unroll
    for (int i = 0; i < 4; i++)
#pragma unroll
        for (int p = 0; p < 4; p++) acc2[i][p] = 0ull;

    for (int k0 = 0; k0 < F_IN; k0 += G1_BK) {
        for (int i = tid; i < G1_BN * G1_BK; i += 256) {
            int n = i >> 5, kk = i & 31;
            int gn = nb + n;
            xs[n][kk] = (gn < N_NODES) ? x[gn * F_IN + k0 + kk] : 0.f;
        }
        for (int i = tid; i < HID * G1_BK; i += 256) {
            int j = i >> 5, col = i & 31;
            ws[col][j] = lin1_w[j * F_IN + k0 + col];
        }
        __syncthreads();
#pragma unroll
        for (int kk = 0; kk < G1_BK; kk++) {
            ulonglong2 wa = *(const ulonglong2*)&ws[kk][jg * 8];
            ulonglong2 wb = *(const ulonglong2*)&ws[kk][jg * 8 + 4];
#pragma unroll
            for (int i = 0; i < 4; i++) {
                unsigned long long xx = pack2(xs[ng * 4 + i][kk]);
                ffma2(acc2[i][0], xx, wa.x);
                ffma2(acc2[i][1], xx, wa.y);
                ffma2(acc2[i][2], xx, wb.x);
                ffma2(acc2[i][3], xx, wb.y);
            }
        }
        __syncthreads();
    }
    float bj[8];
#pragma unroll
    for (int r = 0; r < 8; r++) bj[r] = b1[jg * 8 + r];
#pragma unroll
    for (int i = 0; i < 4; i++) {
        int gn = nb + ng * 4 + i;
        if (gn < N_NODES) {
            float2 p0 = unpack2(acc2[i][0]);
            float2 p1 = unpack2(acc2[i][1]);
            float2 p2 = unpack2(acc2[i][2]);
            float2 p3 = unpack2(acc2[i][3]);
            float4 v0 = make_float4(p0.x + bj[0], p0.y + bj[1], p1.x + bj[2], p1.y + bj[3]);
            float4 v1 = make_float4(p2.x + bj[4], p2.y + bj[5], p3.x + bj[6], p3.y + bj[7]);
            *(float4*)&g_h1f[gn * HID + jg * 8]     = v0;
            *(float4*)&g_h1f[gn * HID + jg * 8 + 4] = v1;
        }
    }
}

// ---------- merged pass1: rsum over src segments; emit fp16 h1 (fp32 exp) -----
__global__ void pass1_kernel() {
    int warp = (blockIdx.x * blockDim.x + threadIdx.x) >> 5;
    int lane = threadIdx.x & 31;
    if (warp >= N_NODES) return;
    int j0 = 2 * lane, j1 = 2 * lane + 1;
    float cpa = g_cp1[j0], cma = g_cm1[j0];
    float cpb = g_cp1[j1], cmb = g_cm1[j1];
    int beg = g_off[warp], end = g_off[warp + 1];
    float a0 = 0.f, a1 = 0.f;
#pragma unroll 2
    for (int i = beg; i < end; i++) {
        float w = __ldg(&g_srcw[i]);
        bool pos = (w >= 0.f);
        a0 += fex2(w * (pos ? cpa : cma));
        a1 += fex2(w * (pos ? cpb : cmb));
    }
    float cpc = g_cp2[lane & 15], cmc = g_cm2[lane & 15];
    float a2 = 0.f;
    int sub = lane >> 4;
#pragma unroll 2
    for (int i = beg + sub; i < end; i += 2) {
        float w = __ldg(&g_srcw[i]);
        a2 += fex2(w * ((w >= 0.f) ? cpc : cmc));
    }
    a2 += __shfl_xor_sync(0xffffffffu, a2, 16);
    float r0 = 1.f / (a0 + 1e-16f);
    float r1 = 1.f / (a1 + 1e-16f);
    float2 hf = *(const float2*)&g_h1f[warp * HID + j0];
    g_h1h[warp * 32 + lane] = __floats2half2_rn(hf.x * r0, hf.y * r1);
    if (lane < 16) g_rsum2[warp * N_CLS + lane] = 1.f / (a2 + 1e-16f);
}

// ---------- layer1 pass2 over dst (fp16 gather) + fused elu + GEMM2 -----------
__global__ void pass2_l1_kernel(const float* __restrict__ lin2_w, const float* __restrict__ lin2_b) {
    __shared__ float ws[HID][N_CLS + 1];
    __shared__ float bs[N_CLS];
    __shared__ float sagg[8][HID + 1];
    int tid = threadIdx.x;
    int wid = tid >> 5;
    int lane = tid & 31;
    int warp = blockIdx.x * 8 + wid;
    for (int i = tid; i < N_CLS * HID; i += 256) {
        int c = i >> 6, k = i & 63;
        ws[k][c] = lin2_w[i];
    }
    if (tid < N_CLS) bs[tid] = lin2_b[tid];

    int j0 = 2 * lane, j1 = 2 * lane + 1;
    float cpa = g_cp1[j0], cma = g_cm1[j0];
    float cpb = g_cp1[j1], cmb = g_cm1[j1];
    const int* doff = g_off + (N_NODES + 1);
    int beg = doff[warp], end = doff[warp + 1];
    float a0 = 0.f, a1 = 0.f;
#pragma unroll 4
    for (int i = beg; i < end; i++) {
        float2 p = __ldg(&g_dstp[i]);
        float w = p.x;
        int s = __float_as_int(p.y);
        bool pos = (w >= 0.f);
        float e0 = fex2(w * (pos ? cpa : cma));
        float e1 = fex2(w * (pos ? cpb : cmb));
        float2 hf = __half22float2(g_h1h[s * 32 + lane]);
        a0 = fmaf(e0, hf.x, a0);
        a1 = fmaf(e1, hf.y, a1);
    }
    sagg[wid][j0] = (a0 > 0.f) ? a0 : (fex2(a0 * LOG2E) - 1.f);
    sagg[wid][j1] = (a1 > 0.f) ? a1 : (fex2(a1 * LOG2E) - 1.f);
    __syncthreads();
    if (tid < 128) {
        int n = tid >> 4, c = tid & 15;
        int node = blockIdx.x * 8 + n;
        float acc = bs[c];
#pragma unroll
        for (int k = 0; k < HID; k++) acc = fmaf(sagg[n][k], ws[k][c], acc);
        g_h2h[node * N_CLS + c] = __float2half(acc * g_rsum2[node * N_CLS + c]);
    }
}

// ---------- layer2 pass2 over dst + fused log_softmax -> out ------------------
__global__ void pass2_l2_kernel(float* __restrict__ out) {
    int warp = (blockIdx.x * blockDim.x + threadIdx.x) >> 5;
    int lane = threadIdx.x & 31;
    if (warp >= N_NODES) return;
    int j = lane & 15, sub = lane >> 4;
    float cp = g_cp2[j], cm = g_cm2[j];
    const int* doff = g_off + (N_NODES + 1);
    int beg = doff[warp], end = doff[warp + 1];
    float a = 0.f;
#pragma unroll 2
    for (int i = beg + sub; i < end; i += 2) {
        float2 p = __ldg(&g_dstp[i]);
        float w = p.x;
        int s = __float_as_int(p.y);
        float c = (w >= 0.f) ? cp : cm;
        a = fmaf(fex2(w * c), __half2float(g_h2h[s * N_CLS + j]), a);
    }
    a += __shfl_xor_sync(0xffffffffu, a, 16);
    float m = a;
#pragma unroll
    for (int k = 8; k >= 1; k >>= 1) m = fmaxf(m, __shfl_xor_sync(0xffffffffu, m, k));
    float ex = fex2((a - m) * LOG2E);
    float ssum = ex;
#pragma unroll
    for (int k = 8; k >= 1; k >>= 1) ssum += __shfl_xor_sync(0xffffffffu, ssum, k);
    float res = a - m - flg2(ssum) * 0.69314718055994531f;
    if (lane < 16) out[warp * N_CLS + lane] = res;
}

// ---------------- launch ------------------------------------------------------
extern "C" void kernel_launch(void* const* d_in, const int* in_sizes, int n_in,
                              void* d_out, int out_size) {
    const float* x      = (const float*)d_in[0];
    const int*   ei     = (const int*)  d_in[1];
    const float* wmul   = (const float*)d_in[2];
    const float* lin1_w = (const float*)d_in[3];
    const float* lin1_b = (const float*)d_in[4];
    const float* m1w0   = (const float*)d_in[5];
    const float* m1w1   = (const float*)d_in[6];
    // d_in[7] = mlp1_b1 (cancels in softmax)
    const float* lin2_w = (const float*)d_in[8];
    const float* lin2_b = (const float*)d_in[9];
    const float* m2w0   = (const float*)d_in[10];
    const float* m2w1   = (const float*)d_in[11];
    // d_in[12] = mlp2_b1 (cancels in softmax)
    float* out = (float*)d_out;

    (void)in_sizes; (void)n_in; (void)out_size;

    const int nblk_scan = (2 * N_NODES + 1023) / 1024;  // 196

    // fork: CSR build (+zero+coefs) on side stream, gemm1 immediately on main
    cudaEventRecord(g_hx.ev0, 0);
    cudaStreamWaitEvent(g_hx.s2, g_hx.ev0, 0);

    prep_zero_kernel<<<197, 1024, 0, g_hx.s2>>>(m1w0, m1w1, m2w0, m2w1);
    hist_kernel<<<(N_EDGES / 4 + 255) / 256, 256, 0, g_hx.s2>>>(ei);
    scan_lb_kernel<<<nblk_scan, 1024, 0, g_hx.s2>>>();
    scatter_src_kernel<<<(N_EDGES / 4 + 255) / 256, 256, 0, g_hx.s2>>>(ei, wmul);
    cudaEventRecord(g_hx.evB, g_hx.s2);
    // dst scatter continues on s2, overlapping with pass1 on the main stream
    scatter_dst_kernel<<<(N_EDGES / 4 + 255) / 256, 256, 0, g_hx.s2>>>(ei, wmul);
    cudaEventRecord(g_hx.evC, g_hx.s2);

    gemm1_kernel<<<(N_NODES + G1_BN - 1) / G1_BN, 256>>>(x, lin1_w, lin1_b);

    // pass1 needs: offsets + srcw + h1f
    cudaStreamWaitEvent(0, g_hx.evB, 0);
    pass1_kernel<<<(N_NODES * 32 + 255) / 256, 256>>>();

    // pass2 needs dstp
    cudaStreamWaitEvent(0, g_hx.evC, 0);
    pass2_l1_kernel<<<(N_NODES * 32 + 255) / 256, 256>>>(lin2_w, lin2_b);
    pass2_l2_kernel<<<(N_NODES * 32 + 255) / 256, 256>>>(out);
}